// round 1
// baseline (speedup 1.0000x reference)
#include <cuda_runtime.h>

// ---------------------------------------------------------------------------
// Compile-time G(3,0,1) blade algebra.
// Basis index order (grade-then-lex, matching the reference):
//   0:1  1:e0 2:e1 3:e2 4:e3  5:e01 6:e02 7:e03 8:e12 9:e13 10:e23
//   11:e012 12:e013 13:e023 14:e123 15:e0123
// Blade = 4-bit mask (bit i = e_i present). Metric: e0^2=0, e1^2=e2^2=e3^2=1.
//
// Structural fact: result mask of a*b is always a^b (repeated indices cancel),
// so for a fixed (output k, right-input j) there is exactly one left-input
// source index. Same for the wedge/join. Everything below folds to literals.
// ---------------------------------------------------------------------------

namespace ga {

__host__ __device__ constexpr int mask_of(int i) {
    const int t[16] = {0, 1, 2, 4, 8, 3, 5, 9, 6, 10, 12, 7, 11, 13, 14, 15};
    return t[i];
}
__host__ __device__ constexpr int idx_of(int m) {
    const int t[16] = {0, 1, 2, 5, 3, 6, 8, 11, 4, 7, 9, 12, 10, 13, 14, 15};
    return t[m];
}
__host__ __device__ constexpr int popc4(int m) {
    return (m & 1) + ((m >> 1) & 1) + ((m >> 2) & 1) + ((m >> 3) & 1);
}
// Sign of reordering e_a e_b into canonical ascending order:
// (-1)^(# pairs (i in a, j in b) with i > j).
__host__ __device__ constexpr int rsign(int a, int b) {
    int cnt = 0;
    for (int i = 1; i < 4; ++i)
        if ((a >> i) & 1) cnt += popc4(b & ((1 << i) - 1));
    return (cnt & 1) ? -1 : 1;
}

// Geometric product: out_gp[k] += gp_coef(k,j) * x[gp_src(k,j)] * y[j].
__host__ __device__ constexpr int gp_coef(int k, int j) {
    const int mk = mask_of(k), mj = mask_of(j);
    const int mi = mk ^ mj;                 // unique left-operand mask
    if (mi & mj & 1) return 0;              // shared e0 -> metric 0
    return rsign(mi, mj);                   // euclidean squares contribute +1
}
__host__ __device__ constexpr int gp_src(int k, int j) {
    return idx_of(mask_of(k) ^ mask_of(j));
}

// Join: out_jn[k] = ref15 * sum_j jn_coef(k,j) * x[jn_src(k,j)] * y[j]
// where join = dual(dual(x) ^ dual(y)), dual = right complement with
// ds(mask) = rsign(mask, ~mask) and dual(x)[idx(~m)] = ds(m)*x[idx(m)].
// Nonzero iff mask_k subset-of mask_j; then left mask mi = mk | ~mj.
__host__ __device__ constexpr int jn_coef(int k, int j) {
    const int mk = mask_of(k), mj = mask_of(j);
    const int nmj = ~mj & 15;
    if (mk & nmj) return 0;                 // requires mk subset of mj
    const int mi = mk | nmj;
    return rsign(~mk & 15, mk)              // dual sign on the output side
         * rsign(mi, ~mi & 15)              // dual sign of x component
         * rsign(mj, ~mj & 15)              // dual sign of y component
         * rsign(~mi & 15, nmj);            // wedge reorder sign
}
__host__ __device__ constexpr int jn_src(int k, int j) {
    const int mk = mask_of(k), mj = mask_of(j);
    return idx_of(mk | (~mj & 15));
}

// -------- compile-time unrolled accumulators (literal register indices) ----

template <int K, int J>
__device__ __forceinline__ float gp_term(const float (&x)[16], const float (&y)[16]) {
    if constexpr (J >= 16) {
        return 0.0f;
    } else {
        float acc = gp_term<K, J + 1>(x, y);
        constexpr int c = gp_coef(K, J);
        constexpr int p = gp_src(K, J);
        if constexpr (c == 1)  acc = fmaf(x[p], y[J], acc);
        if constexpr (c == -1) acc = fmaf(-x[p], y[J], acc);
        return acc;
    }
}

template <int K, int J>
__device__ __forceinline__ float jn_term(const float (&x)[16], const float (&y)[16]) {
    if constexpr (J >= 16) {
        return 0.0f;
    } else {
        float acc = jn_term<K, J + 1>(x, y);
        constexpr int c = jn_coef(K, J);
        constexpr int p = jn_src(K, J);
        if constexpr (c == 1)  acc = fmaf(x[p], y[J], acc);
        if constexpr (c == -1) acc = fmaf(-x[p], y[J], acc);
        return acc;
    }
}

template <int K>
__device__ __forceinline__ void compute(const float (&x)[16], const float (&y)[16],
                                        float r15, float (&o)[32]) {
    if constexpr (K < 16) {
        o[K]      = gp_term<K, 0>(x, y);
        o[16 + K] = r15 * jn_term<K, 0>(x, y);
        compute<K + 1>(x, y, r15, o);
    }
}

}  // namespace ga

// ---------------------------------------------------------------------------
// Kernel: one thread per point. Pure streaming: 2x 64B vec loads, one 4B
// scalar load, 128B vec store, ~273 constant-index FFMAs. HBM-bound.
// ---------------------------------------------------------------------------

__global__ __launch_bounds__(256)
void MVGeometricBilinear_kernel(const float4* __restrict__ x4,
                                const float4* __restrict__ y4,
                                const float* __restrict__ ref,
                                float4* __restrict__ o4,
                                int npts) {
    const int p = blockIdx.x * blockDim.x + threadIdx.x;
    if (p >= npts) return;

    float x[16], y[16];
#pragma unroll
    for (int q = 0; q < 4; ++q) {
        const float4 vx = x4[p * 4 + q];
        const float4 vy = y4[p * 4 + q];
        x[4 * q + 0] = vx.x; x[4 * q + 1] = vx.y;
        x[4 * q + 2] = vx.z; x[4 * q + 3] = vx.w;
        y[4 * q + 0] = vy.x; y[4 * q + 1] = vy.y;
        y[4 * q + 2] = vy.z; y[4 * q + 3] = vy.w;
    }
    const float r15 = __ldg(ref + p * 16 + 15);

    float o[32];
    ga::compute<0>(x, y, r15, o);

#pragma unroll
    for (int q = 0; q < 8; ++q)
        o4[p * 8 + q] = make_float4(o[4 * q + 0], o[4 * q + 1],
                                    o[4 * q + 2], o[4 * q + 3]);
}

extern "C" void kernel_launch(void* const* d_in, const int* in_sizes, int n_in,
                              void* d_out, int out_size) {
    const float* x   = (const float*)d_in[0];
    const float* y   = (const float*)d_in[1];
    const float* ref = (const float*)d_in[2];
    float* out       = (float*)d_out;

    const int npts = in_sizes[0] / 16;  // (B*T) points, 16 components each
    const int threads = 256;
    const int blocks = (npts + threads - 1) / threads;

    MVGeometricBilinear_kernel<<<blocks, threads>>>(
        (const float4*)x, (const float4*)y, ref, (float4*)out, npts);
}